// round 8
// baseline (speedup 1.0000x reference)
#include <cuda_runtime.h>
#include <cuda_fp16.h>
#include <math.h>

#define NN 50000
#define EE 1600000
#define ET (EE + NN)
#define GG 100
#define IN_CH 16
#define H1 4
#define C1 32
#define D1 (H1*C1)
#define C2 32
#define NEG 0.2f

#define DEG_BLOCKS ((EE + 255) / 256)
#define SCAT_BLOCKS ((ET + 255) / 256)
#define GEMM1_BLOCKS ((NN + 63) / 64)

// ---------------- scratch ----------------
__device__ __align__(16) int g_deg[NN + 4];
__device__ __align__(16) int g_rowptr[NN + 4];
__device__ __align__(16) int g_cursor[NN + 4];
__device__ __align__(16) int g_csrsrc[ET];
__device__ __align__(16) __half g_h1h[NN * D1];
__device__ __align__(16) float  g_as1[NN * H1];
__device__ __align__(16) float  g_ad1[NN * H1];
__device__ __align__(16) float  g_out1[NN * D1];
__device__ __align__(16) float  g_h2[NN * C2];
__device__ float g_as2[NN];
__device__ float g_ad2[NN];
__device__ float g_pool[GG * C2];
__device__ float g_cnt[GG];

// ---------------- degree + pool init ----------------
__global__ void k_degree(const int* __restrict__ ei) {
    int b = blockIdx.x;
    if (b < DEG_BLOCKS) {
        int e = b * 256 + threadIdx.x;
        if (e < EE) atomicAdd(&g_deg[ei[EE + e]], 1);
    } else {
        int i = threadIdx.x;
        for (; i < GG * C2; i += 256) g_pool[i] = 0.f;
        int j = threadIdx.x;
        if (j < GG) g_cnt[j] = 0.f;
    }
}

// ---------------- single-block exclusive scan, 4 elems/thread ----------------
__global__ void k_scan() {
    __shared__ int warp_sums[32];
    __shared__ int carry_s;
    int t = threadIdx.x;
    int lane = t & 31, warp = t >> 5;
    if (t == 0) carry_s = 0;
    __syncthreads();
    const int CHUNK = 4096;
    for (int base = 0; base < NN; base += CHUNK) {
        int idx = base + t * 4;
        int4 v4 = make_int4(0, 0, 0, 0);
        if (idx < NN) {
            v4 = *(const int4*)(g_deg + idx);
            *(int4*)(g_deg + idx) = make_int4(0, 0, 0, 0);
            v4.x += 1; v4.y += 1; v4.z += 1; v4.w += 1;   // self loops
        }
        int v = v4.x + v4.y + v4.z + v4.w;
        int incl = v;
        #pragma unroll
        for (int off = 1; off < 32; off <<= 1) {
            int nb = __shfl_up_sync(0xffffffffu, incl, off);
            if (lane >= off) incl += nb;
        }
        if (lane == 31) warp_sums[warp] = incl;
        __syncthreads();
        if (warp == 0) {
            int ws = warp_sums[lane];
            int wincl = ws;
            #pragma unroll
            for (int off = 1; off < 32; off <<= 1) {
                int nb = __shfl_up_sync(0xffffffffu, wincl, off);
                if (lane >= off) wincl += nb;
            }
            warp_sums[lane] = wincl - ws;
        }
        __syncthreads();
        int carry = carry_s;
        int excl = carry + warp_sums[warp] + incl - v;
        if (idx < NN) {
            int4 r;
            r.x = excl;
            r.y = r.x + v4.x;
            r.z = r.y + v4.y;
            r.w = r.z + v4.z;
            *(int4*)(g_rowptr + idx) = r;
            *(int4*)(g_cursor + idx) = r;
        }
        __syncthreads();
        if (t == 1023) carry_s = carry + warp_sums[31] + incl;
        __syncthreads();
    }
    if (t == 0) g_rowptr[NN] = carry_s;
}

// ---------------- GEMM1 body ----------------
__device__ __forceinline__ void gemm1_body(int blk,
                        const float* __restrict__ x,
                        const float* __restrict__ W1,
                        const float* __restrict__ as_w,
                        const float* __restrict__ ad_w,
                        float* sW, float* sAs, float* sAd) {
    int t = threadIdx.x;
    for (int i = t; i < IN_CH * D1; i += 256) sW[i] = W1[i];
    if (t < H1 * C1) { sAs[t] = as_w[t]; sAd[t] = ad_w[t]; }
    __syncthreads();

    int warp = t >> 5, lane = t & 31;
    int h = warp & 3;
    int n = blk * 64 + (warp >> 2) * 32 + lane;
    if (n >= NN) return;

    float xv[16];
    const float4* xp = (const float4*)(x + (size_t)n * IN_CH);
    #pragma unroll
    for (int i = 0; i < 4; i++) {
        float4 r = xp[i];
        xv[4*i]=r.x; xv[4*i+1]=r.y; xv[4*i+2]=r.z; xv[4*i+3]=r.w;
    }
    float acc[C1];
    #pragma unroll
    for (int c = 0; c < C1; c++) acc[c] = 0.f;
    #pragma unroll
    for (int k = 0; k < IN_CH; k++) {
        float xk = xv[k];
        const float* wrow = sW + k * D1 + h * C1;
        #pragma unroll
        for (int c = 0; c < C1; c++) acc[c] += xk * wrow[c];
    }
    float asum = 0.f, dsum = 0.f;
    #pragma unroll
    for (int c = 0; c < C1; c++) { asum += acc[c] * sAs[h*C1+c]; dsum += acc[c] * sAd[h*C1+c]; }
    g_as1[n * H1 + h] = asum;
    g_ad1[n * H1 + h] = dsum;
    uint4 pk[4];
    unsigned* pu = (unsigned*)pk;
    #pragma unroll
    for (int i = 0; i < 16; i++) {
        __half2 hh = __floats2half2_rn(acc[2*i], acc[2*i+1]);
        pu[i] = *(unsigned*)&hh;
    }
    uint4* hp = (uint4*)(g_h1h + (size_t)n * D1 + h * C1);
    #pragma unroll
    for (int i = 0; i < 4; i++) hp[i] = pk[i];
}

// ---------------- scatter + gemm1 fat kernel ----------------
__global__ void __launch_bounds__(256) k_scatter_gemm1(
        const int* __restrict__ ei,
        const float* __restrict__ x,
        const float* __restrict__ W1,
        const float* __restrict__ as_w,
        const float* __restrict__ ad_w) {
    __shared__ float sW[IN_CH * D1 + 2 * H1 * C1];
    int b = blockIdx.x;
    if (b < SCAT_BLOCKS) {
        int idx = b * 256 + threadIdx.x;
        if (idx >= ET) return;
        int src, dst;
        if (idx < EE) { src = ei[idx]; dst = ei[EE + idx]; }
        else          { src = idx - EE; dst = src; }
        int slot = atomicAdd(&g_cursor[dst], 1);
        g_csrsrc[slot] = src;
    } else {
        gemm1_body(b - SCAT_BLOCKS, x, W1, as_w, ad_w,
                   sW, sW + IN_CH * D1, sW + IN_CH * D1 + H1 * C1);
    }
}

__device__ __forceinline__ float lrelu(float e) { return e > 0.f ? e : NEG * e; }
__device__ __forceinline__ float elu(float v)   { return v > 0.f ? v : (__expf(v) - 1.f); }

__device__ __forceinline__ float sel4(float4 a, int q) {
    float w = a.x;
    w = (q == 1) ? a.y : w;
    w = (q == 2) ? a.z : w;
    w = (q == 3) ? a.w : w;
    return w;
}

// ---------------- GAT layer 1: 2 edges/warp-iter in phase B ----------------
// Phase A: lane-parallel exp over 32-edge tile.
// Phase B: warp splits into 2 groups of 16; group g processes edge j+g;
//          lane owns 8 channels (LDG.128 of fp16). Merge groups via shfl_xor(16).
__global__ void __launch_bounds__(256) k_edge1(const float* __restrict__ b1) {
    __shared__ float s_alpha[8][32][4];
    __shared__ int   s_src[8][32];
    int w = threadIdx.x >> 5;
    int lane = threadIdx.x & 31;
    int n = blockIdx.x * 8 + w;
    if (n >= NN) return;
    int beg = g_rowptr[n], end = g_rowptr[n + 1];
    float4 ad = *(const float4*)(g_ad1 + n * 4);
    const __half* hbase = g_h1h;

    int grp = lane >> 4;            // 0/1
    int sub = lane & 15;
    int q2  = sub >> 2;             // head owned in phase B
    int choff = sub * 8;            // channel offset (8 halves = 16B)

    float s0 = 0.f, s1 = 0.f, s2 = 0.f, s3 = 0.f;
    float a[8];
    #pragma unroll
    for (int k = 0; k < 8; k++) a[k] = 0.f;

    for (int base = beg; base < end; base += 32) {
        int i = base + lane;
        int cnt = min(32, end - base);
        // Phase A
        if (i < end) {
            int s = g_csrsrc[i];
            float4 as = *(const float4*)(g_as1 + s * 4);
            float e0 = __expf(lrelu(as.x + ad.x));
            float e1 = __expf(lrelu(as.y + ad.y));
            float e2 = __expf(lrelu(as.z + ad.z));
            float e3 = __expf(lrelu(as.w + ad.w));
            s0 += e0; s1 += e1; s2 += e2; s3 += e3;
            s_src[w][lane] = s;
            s_alpha[w][lane][0] = e0;
            s_alpha[w][lane][1] = e1;
            s_alpha[w][lane][2] = e2;
            s_alpha[w][lane][3] = e3;
        }
        __syncwarp();
        // Phase B: 2 edges per iteration (one per 16-lane group)
        int j = 0;
        for (; j + 2 <= cnt; j += 2) {
            int   sj = s_src[w][j + grp];
            float wj = s_alpha[w][j + grp][q2];
            uint4 p = *(const uint4*)(hbase + (size_t)sj * D1 + choff);
            float2 f0 = __half22float2(*(__half2*)&p.x);
            float2 f1 = __half22float2(*(__half2*)&p.y);
            float2 f2 = __half22float2(*(__half2*)&p.z);
            float2 f3 = __half22float2(*(__half2*)&p.w);
            a[0] += wj * f0.x; a[1] += wj * f0.y;
            a[2] += wj * f1.x; a[3] += wj * f1.y;
            a[4] += wj * f2.x; a[5] += wj * f2.y;
            a[6] += wj * f3.x; a[7] += wj * f3.y;
        }
        if (j < cnt && grp == 0) {   // odd tail: group 0 only
            int   sj = s_src[w][j];
            float wj = s_alpha[w][j][q2];
            uint4 p = *(const uint4*)(hbase + (size_t)sj * D1 + choff);
            float2 f0 = __half22float2(*(__half2*)&p.x);
            float2 f1 = __half22float2(*(__half2*)&p.y);
            float2 f2 = __half22float2(*(__half2*)&p.z);
            float2 f3 = __half22float2(*(__half2*)&p.w);
            a[0] += wj * f0.x; a[1] += wj * f0.y;
            a[2] += wj * f1.x; a[3] += wj * f1.y;
            a[4] += wj * f2.x; a[5] += wj * f2.y;
            a[6] += wj * f3.x; a[7] += wj * f3.y;
        }
        __syncwarp();
    }
    // merge the two groups (same channels, different edges)
    #pragma unroll
    for (int k = 0; k < 8; k++) a[k] += __shfl_xor_sync(0xffffffffu, a[k], 16);
    // per-head softmax denominators
    #pragma unroll
    for (int off = 16; off; off >>= 1) {
        s0 += __shfl_xor_sync(0xffffffffu, s0, off);
        s1 += __shfl_xor_sync(0xffffffffu, s1, off);
        s2 += __shfl_xor_sync(0xffffffffu, s2, off);
        s3 += __shfl_xor_sync(0xffffffffu, s3, off);
    }
    if (grp == 0) {
        float inv = sel4(make_float4(1.f/(s0+1e-16f), 1.f/(s1+1e-16f),
                                     1.f/(s2+1e-16f), 1.f/(s3+1e-16f)), q2);
        float* op = g_out1 + (size_t)n * D1 + choff;
        const float* bp = b1 + choff;
        float4 o0, o1;
        o0.x = elu(a[0] * inv + bp[0]);
        o0.y = elu(a[1] * inv + bp[1]);
        o0.z = elu(a[2] * inv + bp[2]);
        o0.w = elu(a[3] * inv + bp[3]);
        o1.x = elu(a[4] * inv + bp[4]);
        o1.y = elu(a[5] * inv + bp[5]);
        o1.z = elu(a[6] * inv + bp[6]);
        o1.w = elu(a[7] * inv + bp[7]);
        *(float4*)op = o0;
        *(float4*)(op + 4) = o1;
    }
}

// ---------------- GEMM2 + attention logits ----------------
__global__ void k_gemm2(const float* __restrict__ W2,
                        const float* __restrict__ as_w,
                        const float* __restrict__ ad_w) {
    __shared__ float sW[D1 * C2];
    __shared__ float sAs[C2], sAd[C2];
    int t = threadIdx.x;
    for (int i = t; i < D1 * C2; i += 256) sW[i] = W2[i];
    if (t < C2) { sAs[t] = as_w[t]; sAd[t] = ad_w[t]; }
    __syncthreads();
    int n = blockIdx.x * blockDim.x + t;
    if (n >= NN) return;

    float acc[C2];
    #pragma unroll
    for (int c = 0; c < C2; c++) acc[c] = 0.f;
    const float4* xp = (const float4*)(g_out1 + (size_t)n * D1);
    for (int k4 = 0; k4 < 32; k4++) {
        float4 xv = xp[k4];
        const float* w0 = sW + (k4 * 4) * C2;
        #pragma unroll
        for (int c = 0; c < C2; c++) {
            acc[c] += xv.x * w0[c] + xv.y * w0[C2 + c] + xv.z * w0[2*C2 + c] + xv.w * w0[3*C2 + c];
        }
    }
    float asum = 0.f, dsum = 0.f;
    #pragma unroll
    for (int c = 0; c < C2; c++) { asum += acc[c] * sAs[c]; dsum += acc[c] * sAd[c]; }
    g_as2[n] = asum;
    g_ad2[n] = dsum;
    float4* hp = (float4*)(g_h2 + (size_t)n * C2);
    #pragma unroll
    for (int i = 0; i < 8; i++) hp[i] = make_float4(acc[4*i], acc[4*i+1], acc[4*i+2], acc[4*i+3]);
}

// ---------------- GAT layer 2 + pooling: 4 edges/warp-iter ----------------
__global__ void __launch_bounds__(256) k_edge2(const float* __restrict__ b2,
                        const int* __restrict__ batch) {
    __shared__ float s_alpha[8][32];
    __shared__ int   s_src[8][32];
    int w = threadIdx.x >> 5;
    int lane = threadIdx.x & 31;
    int n = blockIdx.x * 8 + w;
    if (n >= NN) return;
    int beg = g_rowptr[n], end = g_rowptr[n + 1];
    float ad = g_ad2[n];

    int grp = lane >> 3;            // 0..3
    int sub = lane & 7;
    int choff = sub * 4;            // 4 floats

    float ssum = 0.f;
    float4 acc = make_float4(0.f, 0.f, 0.f, 0.f);
    for (int base = beg; base < end; base += 32) {
        int i = base + lane;
        int cnt = min(32, end - base);
        if (i < end) {
            int s = g_csrsrc[i];
            float e = __expf(lrelu(g_as2[s] + ad));
            ssum += e;
            s_src[w][lane] = s;
            s_alpha[w][lane] = e;
        }
        __syncwarp();
        int j = 0;
        for (; j + 4 <= cnt; j += 4) {
            int   sj = s_src[w][j + grp];
            float wj = s_alpha[w][j + grp];
            float4 f = *(const float4*)(g_h2 + (size_t)sj * C2 + choff);
            acc.x += wj * f.x; acc.y += wj * f.y; acc.z += wj * f.z; acc.w += wj * f.w;
        }
        int rem = cnt - j;
        if (grp < rem) {
            int   sj = s_src[w][j + grp];
            float wj = s_alpha[w][j + grp];
            float4 f = *(const float4*)(g_h2 + (size_t)sj * C2 + choff);
            acc.x += wj * f.x; acc.y += wj * f.y; acc.z += wj * f.z; acc.w += wj * f.w;
        }
        __syncwarp();
    }
    // merge 4 groups (same channels)
    #pragma unroll
    for (int off = 8; off <= 16; off <<= 1) {
        acc.x += __shfl_xor_sync(0xffffffffu, acc.x, off);
        acc.y += __shfl_xor_sync(0xffffffffu, acc.y, off);
        acc.z += __shfl_xor_sync(0xffffffffu, acc.z, off);
        acc.w += __shfl_xor_sync(0xffffffffu, acc.w, off);
    }
    #pragma unroll
    for (int off = 16; off; off >>= 1) ssum += __shfl_xor_sync(0xffffffffu, ssum, off);
    float inv = 1.f / (ssum + 1e-16f);
    int gid = batch[n];
    if (grp == 0) {
        const float* bp = b2 + choff;
        float* pp = g_pool + gid * C2 + choff;
        atomicAdd(pp + 0, elu(acc.x * inv + bp[0]));
        atomicAdd(pp + 1, elu(acc.y * inv + bp[1]));
        atomicAdd(pp + 2, elu(acc.z * inv + bp[2]));
        atomicAdd(pp + 3, elu(acc.w * inv + bp[3]));
        if (sub == 0) atomicAdd(&g_cnt[gid], 1.0f);
    }
}

// ---------------- MLP head ----------------
__global__ void k_head(const float* __restrict__ Wh1, const float* __restrict__ bh1,
                       const float* __restrict__ Wh2, const float* __restrict__ bh2,
                       float* __restrict__ out) {
    int g = blockIdx.x * blockDim.x + threadIdx.x;
    if (g >= GG) return;
    float cnt = fmaxf(g_cnt[g], 1.0f);
    float invc = 1.f / cnt;
    float p[C2];
    #pragma unroll
    for (int c = 0; c < C2; c++) p[c] = g_pool[g * C2 + c] * invc;
    float o = bh2[0];
    for (int j = 0; j < 64; j++) {
        float a = bh1[j];
        #pragma unroll
        for (int c = 0; c < C2; c++) a += p[c] * Wh1[c * 64 + j];
        a = fmaxf(a, 0.f);
        o += a * Wh2[j];
    }
    out[g] = o;
}

// ---------------- launch ----------------
extern "C" void kernel_launch(void* const* d_in, const int* in_sizes, int n_in,
                              void* d_out, int out_size) {
    const float* x     = (const float*)d_in[0];
    const int*   ei    = (const int*)d_in[1];
    const int*   batch = (const int*)d_in[2];
    const float* W1   = (const float*)d_in[3];
    const float* as1  = (const float*)d_in[4];
    const float* ad1  = (const float*)d_in[5];
    const float* b1   = (const float*)d_in[6];
    const float* W2   = (const float*)d_in[7];
    const float* as2  = (const float*)d_in[8];
    const float* ad2  = (const float*)d_in[9];
    const float* b2   = (const float*)d_in[10];
    const float* Wh1  = (const float*)d_in[11];
    const float* bh1  = (const float*)d_in[12];
    const float* Wh2  = (const float*)d_in[13];
    const float* bh2  = (const float*)d_in[14];
    float* out = (float*)d_out;

    k_degree<<<DEG_BLOCKS + 1, 256>>>(ei);
    k_scan<<<1, 1024>>>();
    k_scatter_gemm1<<<SCAT_BLOCKS + GEMM1_BLOCKS, 256>>>(ei, x, W1, as1, ad1);
    k_edge1<<<(NN + 7) / 8, 256>>>(b1);
    k_gemm2<<<(NN + 255) / 256, 256>>>(W2, as2, ad2);
    k_edge2<<<(NN + 7) / 8, 256>>>(b2, batch);
    k_head<<<1, 128>>>(Wh1, bh1, Wh2, bh2, out);
}

// round 9
// speedup vs baseline: 1.1295x; 1.1295x over previous
#include <cuda_runtime.h>
#include <cuda_fp16.h>
#include <math.h>

#define NN 50000
#define EE 1600000
#define ET (EE + NN)
#define GG 100
#define IN_CH 16
#define H1 4
#define C1 32
#define D1 (H1*C1)
#define C2 32
#define NEG 0.2f

#define DEG_BLOCKS ((EE + 255) / 256)
#define SCAT_BLOCKS ((ET + 255) / 256)
#define GEMM1_BLOCKS ((NN + 63) / 64)

// ---------------- scratch ----------------
__device__ __align__(16) int g_deg[NN + 4];
__device__ __align__(16) int g_rowptr[NN + 4];
__device__ __align__(16) int g_cursor[NN + 4];
__device__ __align__(16) int g_csrsrc[ET];
__device__ __align__(16) __half g_h1h[NN * D1];
__device__ __align__(16) float  g_as1[NN * H1];
__device__ __align__(16) float  g_ad1[NN * H1];
__device__ __align__(16) float  g_out1[NN * D1];
__device__ __align__(16) float  g_h2[NN * C2];
__device__ float g_as2[NN];
__device__ float g_ad2[NN];
__device__ float g_pool[GG * C2];
__device__ float g_cnt[GG];

// ---------------- degree + pool init ----------------
__global__ void k_degree(const int* __restrict__ ei) {
    int b = blockIdx.x;
    if (b < DEG_BLOCKS) {
        int e = b * 256 + threadIdx.x;
        if (e < EE) atomicAdd(&g_deg[ei[EE + e]], 1);
    } else {
        int i = threadIdx.x;
        for (; i < GG * C2; i += 256) g_pool[i] = 0.f;
        int j = threadIdx.x;
        if (j < GG) g_cnt[j] = 0.f;
    }
}

// ---------------- single-block exclusive scan, 4 elems/thread ----------------
__global__ void k_scan() {
    __shared__ int warp_sums[32];
    __shared__ int carry_s;
    int t = threadIdx.x;
    int lane = t & 31, warp = t >> 5;
    if (t == 0) carry_s = 0;
    __syncthreads();
    const int CHUNK = 4096;
    for (int base = 0; base < NN; base += CHUNK) {
        int idx = base + t * 4;
        int4 v4 = make_int4(0, 0, 0, 0);
        if (idx < NN) {
            v4 = *(const int4*)(g_deg + idx);
            *(int4*)(g_deg + idx) = make_int4(0, 0, 0, 0);
            v4.x += 1; v4.y += 1; v4.z += 1; v4.w += 1;   // self loops
        }
        int v = v4.x + v4.y + v4.z + v4.w;
        int incl = v;
        #pragma unroll
        for (int off = 1; off < 32; off <<= 1) {
            int nb = __shfl_up_sync(0xffffffffu, incl, off);
            if (lane >= off) incl += nb;
        }
        if (lane == 31) warp_sums[warp] = incl;
        __syncthreads();
        if (warp == 0) {
            int ws = warp_sums[lane];
            int wincl = ws;
            #pragma unroll
            for (int off = 1; off < 32; off <<= 1) {
                int nb = __shfl_up_sync(0xffffffffu, wincl, off);
                if (lane >= off) wincl += nb;
            }
            warp_sums[lane] = wincl - ws;
        }
        __syncthreads();
        int carry = carry_s;
        int excl = carry + warp_sums[warp] + incl - v;
        if (idx < NN) {
            int4 r;
            r.x = excl;
            r.y = r.x + v4.x;
            r.z = r.y + v4.y;
            r.w = r.z + v4.z;
            *(int4*)(g_rowptr + idx) = r;
            *(int4*)(g_cursor + idx) = r;
        }
        __syncthreads();
        if (t == 1023) carry_s = carry + warp_sums[31] + incl;
        __syncthreads();
    }
    if (t == 0) g_rowptr[NN] = carry_s;
}

// ---------------- GEMM1 body ----------------
__device__ __forceinline__ void gemm1_body(int blk,
                        const float* __restrict__ x,
                        const float* __restrict__ W1,
                        const float* __restrict__ as_w,
                        const float* __restrict__ ad_w,
                        float* sW, float* sAs, float* sAd) {
    int t = threadIdx.x;
    for (int i = t; i < IN_CH * D1; i += 256) sW[i] = W1[i];
    if (t < H1 * C1) { sAs[t] = as_w[t]; sAd[t] = ad_w[t]; }
    __syncthreads();

    int warp = t >> 5, lane = t & 31;
    int h = warp & 3;
    int n = blk * 64 + (warp >> 2) * 32 + lane;
    if (n >= NN) return;

    float xv[16];
    const float4* xp = (const float4*)(x + (size_t)n * IN_CH);
    #pragma unroll
    for (int i = 0; i < 4; i++) {
        float4 r = xp[i];
        xv[4*i]=r.x; xv[4*i+1]=r.y; xv[4*i+2]=r.z; xv[4*i+3]=r.w;
    }
    float acc[C1];
    #pragma unroll
    for (int c = 0; c < C1; c++) acc[c] = 0.f;
    #pragma unroll
    for (int k = 0; k < IN_CH; k++) {
        float xk = xv[k];
        const float* wrow = sW + k * D1 + h * C1;
        #pragma unroll
        for (int c = 0; c < C1; c++) acc[c] += xk * wrow[c];
    }
    float asum = 0.f, dsum = 0.f;
    #pragma unroll
    for (int c = 0; c < C1; c++) { asum += acc[c] * sAs[h*C1+c]; dsum += acc[c] * sAd[h*C1+c]; }
    g_as1[n * H1 + h] = asum;
    g_ad1[n * H1 + h] = dsum;
    uint4 pk[4];
    unsigned* pu = (unsigned*)pk;
    #pragma unroll
    for (int i = 0; i < 16; i++) {
        __half2 hh = __floats2half2_rn(acc[2*i], acc[2*i+1]);
        pu[i] = *(unsigned*)&hh;
    }
    uint4* hp = (uint4*)(g_h1h + (size_t)n * D1 + h * C1);
    #pragma unroll
    for (int i = 0; i < 4; i++) hp[i] = pk[i];
}

// ---------------- scatter + gemm1 fat kernel ----------------
__global__ void __launch_bounds__(256) k_scatter_gemm1(
        const int* __restrict__ ei,
        const float* __restrict__ x,
        const float* __restrict__ W1,
        const float* __restrict__ as_w,
        const float* __restrict__ ad_w) {
    __shared__ float sW[IN_CH * D1 + 2 * H1 * C1];
    int b = blockIdx.x;
    if (b < SCAT_BLOCKS) {
        int idx = b * 256 + threadIdx.x;
        if (idx >= ET) return;
        int src, dst;
        if (idx < EE) { src = ei[idx]; dst = ei[EE + idx]; }
        else          { src = idx - EE; dst = src; }
        int slot = atomicAdd(&g_cursor[dst], 1);
        g_csrsrc[slot] = src;
    } else {
        gemm1_body(b - SCAT_BLOCKS, x, W1, as_w, ad_w,
                   sW, sW + IN_CH * D1, sW + IN_CH * D1 + H1 * C1);
    }
}

__device__ __forceinline__ float lrelu(float e) { return e > 0.f ? e : NEG * e; }
__device__ __forceinline__ float elu(float v)   { return v > 0.f ? v : (__expf(v) - 1.f); }

__device__ __forceinline__ float sel4(float4 a, int q) {
    float w = a.x;
    w = (q == 1) ? a.y : w;
    w = (q == 2) ? a.z : w;
    w = (q == 3) ? a.w : w;
    return w;
}

// ---------------- GAT layer 1: 2 edges/warp-iter, packed smem, x2 unroll ----------------
__global__ void __launch_bounds__(256) k_edge1(const float* __restrict__ b1) {
    __shared__ int2 s_pk[8][32][4];   // [warp][edge][head] = (src, bits(e_head))
    int w = threadIdx.x >> 5;
    int lane = threadIdx.x & 31;
    int n = blockIdx.x * 8 + w;
    if (n >= NN) return;
    int beg = g_rowptr[n], end = g_rowptr[n + 1];
    float4 ad = *(const float4*)(g_ad1 + n * 4);
    const __half* hbase = g_h1h;

    int grp = lane >> 4;            // 0/1
    int sub = lane & 15;
    int q2  = sub >> 2;             // head owned in phase B
    int choff = sub * 8;            // 8 halves = 16B

    float s0 = 0.f, s1 = 0.f, s2 = 0.f, s3 = 0.f;
    float a[8];
    #pragma unroll
    for (int k = 0; k < 8; k++) a[k] = 0.f;

    for (int base = beg; base < end; base += 32) {
        int i = base + lane;
        int cnt = min(32, end - base);
        // Phase A: lane-parallel exp
        if (i < end) {
            int s = g_csrsrc[i];
            float4 as = *(const float4*)(g_as1 + s * 4);
            float e0 = __expf(lrelu(as.x + ad.x));
            float e1 = __expf(lrelu(as.y + ad.y));
            float e2 = __expf(lrelu(as.z + ad.z));
            float e3 = __expf(lrelu(as.w + ad.w));
            s0 += e0; s1 += e1; s2 += e2; s3 += e3;
            s_pk[w][lane][0] = make_int2(s, __float_as_int(e0));
            s_pk[w][lane][1] = make_int2(s, __float_as_int(e1));
            s_pk[w][lane][2] = make_int2(s, __float_as_int(e2));
            s_pk[w][lane][3] = make_int2(s, __float_as_int(e3));
        }
        __syncwarp();
        // Phase B: 2 edges per warp-iter, unrolled x2 (2 LDGs in flight per group)
        int j = 0;
        for (; j + 4 <= cnt; j += 4) {
            int2 pkA = s_pk[w][j + grp][q2];
            int2 pkB = s_pk[w][j + 2 + grp][q2];
            uint4 pA = *(const uint4*)(hbase + (size_t)pkA.x * D1 + choff);
            uint4 pB = *(const uint4*)(hbase + (size_t)pkB.x * D1 + choff);
            float wA = __int_as_float(pkA.y);
            float wB = __int_as_float(pkB.y);
            float2 f;
            f = __half22float2(*(__half2*)&pA.x); a[0] += wA * f.x; a[1] += wA * f.y;
            f = __half22float2(*(__half2*)&pA.y); a[2] += wA * f.x; a[3] += wA * f.y;
            f = __half22float2(*(__half2*)&pA.z); a[4] += wA * f.x; a[5] += wA * f.y;
            f = __half22float2(*(__half2*)&pA.w); a[6] += wA * f.x; a[7] += wA * f.y;
            f = __half22float2(*(__half2*)&pB.x); a[0] += wB * f.x; a[1] += wB * f.y;
            f = __half22float2(*(__half2*)&pB.y); a[2] += wB * f.x; a[3] += wB * f.y;
            f = __half22float2(*(__half2*)&pB.z); a[4] += wB * f.x; a[5] += wB * f.y;
            f = __half22float2(*(__half2*)&pB.w); a[6] += wB * f.x; a[7] += wB * f.y;
        }
        for (; j + 2 <= cnt; j += 2) {
            int2 pk = s_pk[w][j + grp][q2];
            uint4 p = *(const uint4*)(hbase + (size_t)pk.x * D1 + choff);
            float wj = __int_as_float(pk.y);
            float2 f;
            f = __half22float2(*(__half2*)&p.x); a[0] += wj * f.x; a[1] += wj * f.y;
            f = __half22float2(*(__half2*)&p.y); a[2] += wj * f.x; a[3] += wj * f.y;
            f = __half22float2(*(__half2*)&p.z); a[4] += wj * f.x; a[5] += wj * f.y;
            f = __half22float2(*(__half2*)&p.w); a[6] += wj * f.x; a[7] += wj * f.y;
        }
        if (j < cnt && grp == 0) {   // odd tail
            int2 pk = s_pk[w][j][q2];
            uint4 p = *(const uint4*)(hbase + (size_t)pk.x * D1 + choff);
            float wj = __int_as_float(pk.y);
            float2 f;
            f = __half22float2(*(__half2*)&p.x); a[0] += wj * f.x; a[1] += wj * f.y;
            f = __half22float2(*(__half2*)&p.y); a[2] += wj * f.x; a[3] += wj * f.y;
            f = __half22float2(*(__half2*)&p.z); a[4] += wj * f.x; a[5] += wj * f.y;
            f = __half22float2(*(__half2*)&p.w); a[6] += wj * f.x; a[7] += wj * f.y;
        }
        __syncwarp();
    }
    #pragma unroll
    for (int k = 0; k < 8; k++) a[k] += __shfl_xor_sync(0xffffffffu, a[k], 16);
    #pragma unroll
    for (int off = 16; off; off >>= 1) {
        s0 += __shfl_xor_sync(0xffffffffu, s0, off);
        s1 += __shfl_xor_sync(0xffffffffu, s1, off);
        s2 += __shfl_xor_sync(0xffffffffu, s2, off);
        s3 += __shfl_xor_sync(0xffffffffu, s3, off);
    }
    if (grp == 0) {
        float inv = sel4(make_float4(1.f/(s0+1e-16f), 1.f/(s1+1e-16f),
                                     1.f/(s2+1e-16f), 1.f/(s3+1e-16f)), q2);
        float* op = g_out1 + (size_t)n * D1 + choff;
        const float* bp = b1 + choff;
        float4 o0, o1;
        o0.x = elu(a[0] * inv + bp[0]);
        o0.y = elu(a[1] * inv + bp[1]);
        o0.z = elu(a[2] * inv + bp[2]);
        o0.w = elu(a[3] * inv + bp[3]);
        o1.x = elu(a[4] * inv + bp[4]);
        o1.y = elu(a[5] * inv + bp[5]);
        o1.z = elu(a[6] * inv + bp[6]);
        o1.w = elu(a[7] * inv + bp[7]);
        *(float4*)op = o0;
        *(float4*)(op + 4) = o1;
    }
}

// ---------------- GEMM2 + attention logits ----------------
__global__ void k_gemm2(const float* __restrict__ W2,
                        const float* __restrict__ as_w,
                        const float* __restrict__ ad_w) {
    __shared__ float sW[D1 * C2];
    __shared__ float sAs[C2], sAd[C2];
    int t = threadIdx.x;
    for (int i = t; i < D1 * C2; i += 256) sW[i] = W2[i];
    if (t < C2) { sAs[t] = as_w[t]; sAd[t] = ad_w[t]; }
    __syncthreads();
    int n = blockIdx.x * blockDim.x + t;
    if (n >= NN) return;

    float acc[C2];
    #pragma unroll
    for (int c = 0; c < C2; c++) acc[c] = 0.f;
    const float4* xp = (const float4*)(g_out1 + (size_t)n * D1);
    for (int k4 = 0; k4 < 32; k4++) {
        float4 xv = xp[k4];
        const float* w0 = sW + (k4 * 4) * C2;
        #pragma unroll
        for (int c = 0; c < C2; c++) {
            acc[c] += xv.x * w0[c] + xv.y * w0[C2 + c] + xv.z * w0[2*C2 + c] + xv.w * w0[3*C2 + c];
        }
    }
    float asum = 0.f, dsum = 0.f;
    #pragma unroll
    for (int c = 0; c < C2; c++) { asum += acc[c] * sAs[c]; dsum += acc[c] * sAd[c]; }
    g_as2[n] = asum;
    g_ad2[n] = dsum;
    float4* hp = (float4*)(g_h2 + (size_t)n * C2);
    #pragma unroll
    for (int i = 0; i < 8; i++) hp[i] = make_float4(acc[4*i], acc[4*i+1], acc[4*i+2], acc[4*i+3]);
}

// ---------------- GAT layer 2 + pooling: warp-uniform 8-deep pipeline (R7 form) ----------------
__global__ void __launch_bounds__(256) k_edge2(const float* __restrict__ b2,
                        const int* __restrict__ batch) {
    __shared__ int2 s_pk[8][32];    // (src, bits(alpha))
    int w = threadIdx.x >> 5;
    int lane = threadIdx.x & 31;
    int n = blockIdx.x * 8 + w;
    if (n >= NN) return;
    int beg = g_rowptr[n], end = g_rowptr[n + 1];
    float ad = g_ad2[n];

    float ssum = 0.f, acc = 0.f;
    for (int base = beg; base < end; base += 32) {
        int i = base + lane;
        int cnt = min(32, end - base);
        if (i < end) {
            int s = g_csrsrc[i];
            float e = __expf(lrelu(g_as2[s] + ad));
            ssum += e;
            s_pk[w][lane] = make_int2(s, __float_as_int(e));
        }
        __syncwarp();
        int j = 0;
        for (; j + 8 <= cnt; j += 8) {
            int2 pk[8];
            #pragma unroll
            for (int k = 0; k < 8; k++) pk[k] = s_pk[w][j + k];
            float fj[8];
            #pragma unroll
            for (int k = 0; k < 8; k++) fj[k] = g_h2[(size_t)pk[k].x * C2 + lane];
            #pragma unroll
            for (int k = 0; k < 8; k++) acc += __int_as_float(pk[k].y) * fj[k];
        }
        for (; j < cnt; j++) {
            int2 pk = s_pk[w][j];
            acc += __int_as_float(pk.y) * g_h2[(size_t)pk.x * C2 + lane];
        }
        __syncwarp();
    }
    #pragma unroll
    for (int off = 16; off; off >>= 1) ssum += __shfl_xor_sync(0xffffffffu, ssum, off);
    float inv = 1.f / (ssum + 1e-16f);
    float v = elu(acc * inv + b2[lane]);
    int gid = batch[n];
    atomicAdd(&g_pool[gid * C2 + lane], v);
    if (lane == 0) atomicAdd(&g_cnt[gid], 1.0f);
}

// ---------------- MLP head ----------------
__global__ void k_head(const float* __restrict__ Wh1, const float* __restrict__ bh1,
                       const float* __restrict__ Wh2, const float* __restrict__ bh2,
                       float* __restrict__ out) {
    int g = blockIdx.x * blockDim.x + threadIdx.x;
    if (g >= GG) return;
    float cnt = fmaxf(g_cnt[g], 1.0f);
    float invc = 1.f / cnt;
    float p[C2];
    #pragma unroll
    for (int c = 0; c < C2; c++) p[c] = g_pool[g * C2 + c] * invc;
    float o = bh2[0];
    for (int j = 0; j < 64; j++) {
        float a = bh1[j];
        #pragma unroll
        for (int c = 0; c < C2; c++) a += p[c] * Wh1[c * 64 + j];
        a = fmaxf(a, 0.f);
        o += a * Wh2[j];
    }
    out[g] = o;
}

// ---------------- launch ----------------
extern "C" void kernel_launch(void* const* d_in, const int* in_sizes, int n_in,
                              void* d_out, int out_size) {
    const float* x     = (const float*)d_in[0];
    const int*   ei    = (const int*)d_in[1];
    const int*   batch = (const int*)d_in[2];
    const float* W1   = (const float*)d_in[3];
    const float* as1  = (const float*)d_in[4];
    const float* ad1  = (const float*)d_in[5];
    const float* b1   = (const float*)d_in[6];
    const float* W2   = (const float*)d_in[7];
    const float* as2  = (const float*)d_in[8];
    const float* ad2  = (const float*)d_in[9];
    const float* b2   = (const float*)d_in[10];
    const float* Wh1  = (const float*)d_in[11];
    const float* bh1  = (const float*)d_in[12];
    const float* Wh2  = (const float*)d_in[13];
    const float* bh2  = (const float*)d_in[14];
    float* out = (float*)d_out;

    k_degree<<<DEG_BLOCKS + 1, 256>>>(ei);
    k_scan<<<1, 1024>>>();
    k_scatter_gemm1<<<SCAT_BLOCKS + GEMM1_BLOCKS, 256>>>(ei, x, W1, as1, ad1);
    k_edge1<<<(NN + 7) / 8, 256>>>(b1);
    k_gemm2<<<(NN + 255) / 256, 256>>>(W2, as2, ad2);
    k_edge2<<<(NN + 7) / 8, 256>>>(b2, batch);
    k_head<<<1, 128>>>(Wh1, bh1, Wh2, bh2, out);
}

// round 10
// speedup vs baseline: 1.2232x; 1.0829x over previous
#include <cuda_runtime.h>
#include <cuda_fp16.h>
#include <math.h>

#define NN 50000
#define EE 1600000
#define ET (EE + NN)
#define GG 100
#define IN_CH 16
#define H1 4
#define C1 32
#define D1 (H1*C1)
#define C2 32
#define NEG 0.2f

#define DEG_BLOCKS ((EE + 255) / 256)
#define SCAT_BLOCKS ((ET + 255) / 256)
#define GEMM1_BLOCKS ((NN + 63) / 64)

// ---------------- scratch ----------------
__device__ __align__(16) int g_deg[NN + 4];
__device__ __align__(16) int g_rowptr[NN + 4];
__device__ __align__(16) int g_cursor[NN + 4];
__device__ __align__(16) int g_csrsrc[ET];
__device__ __align__(16) __half g_h1h[NN * D1];
__device__ __align__(16) float  g_as1[NN * H1];
__device__ __align__(16) float  g_ad1[NN * H1];
__device__ __align__(16) __half g_out1h[NN * D1];   // fp16 layer-1 output
__device__ __align__(16) __half g_h2h[NN * C2];     // fp16 layer-2 features
__device__ float g_as2[NN];
__device__ float g_ad2[NN];
__device__ float g_pool[GG * C2];
__device__ float g_cnt[GG];

// ---------------- degree + pool init ----------------
__global__ void k_degree(const int* __restrict__ ei) {
    int b = blockIdx.x;
    if (b < DEG_BLOCKS) {
        int e = b * 256 + threadIdx.x;
        if (e < EE) atomicAdd(&g_deg[ei[EE + e]], 1);
    } else {
        int i = threadIdx.x;
        for (; i < GG * C2; i += 256) g_pool[i] = 0.f;
        int j = threadIdx.x;
        if (j < GG) g_cnt[j] = 0.f;
    }
}

// ---------------- single-block exclusive scan, 4 elems/thread ----------------
__global__ void k_scan() {
    __shared__ int warp_sums[32];
    __shared__ int carry_s;
    int t = threadIdx.x;
    int lane = t & 31, warp = t >> 5;
    if (t == 0) carry_s = 0;
    __syncthreads();
    const int CHUNK = 4096;
    for (int base = 0; base < NN; base += CHUNK) {
        int idx = base + t * 4;
        int4 v4 = make_int4(0, 0, 0, 0);
        if (idx < NN) {
            v4 = *(const int4*)(g_deg + idx);
            *(int4*)(g_deg + idx) = make_int4(0, 0, 0, 0);
            v4.x += 1; v4.y += 1; v4.z += 1; v4.w += 1;   // self loops
        }
        int v = v4.x + v4.y + v4.z + v4.w;
        int incl = v;
        #pragma unroll
        for (int off = 1; off < 32; off <<= 1) {
            int nb = __shfl_up_sync(0xffffffffu, incl, off);
            if (lane >= off) incl += nb;
        }
        if (lane == 31) warp_sums[warp] = incl;
        __syncthreads();
        if (warp == 0) {
            int ws = warp_sums[lane];
            int wincl = ws;
            #pragma unroll
            for (int off = 1; off < 32; off <<= 1) {
                int nb = __shfl_up_sync(0xffffffffu, wincl, off);
                if (lane >= off) wincl += nb;
            }
            warp_sums[lane] = wincl - ws;
        }
        __syncthreads();
        int carry = carry_s;
        int excl = carry + warp_sums[warp] + incl - v;
        if (idx < NN) {
            int4 r;
            r.x = excl;
            r.y = r.x + v4.x;
            r.z = r.y + v4.y;
            r.w = r.z + v4.z;
            *(int4*)(g_rowptr + idx) = r;
            *(int4*)(g_cursor + idx) = r;
        }
        __syncthreads();
        if (t == 1023) carry_s = carry + warp_sums[31] + incl;
        __syncthreads();
    }
    if (t == 0) g_rowptr[NN] = carry_s;
}

// ---------------- GEMM1 body ----------------
__device__ __forceinline__ void gemm1_body(int blk,
                        const float* __restrict__ x,
                        const float* __restrict__ W1,
                        const float* __restrict__ as_w,
                        const float* __restrict__ ad_w,
                        float* sW, float* sAs, float* sAd) {
    int t = threadIdx.x;
    for (int i = t; i < IN_CH * D1; i += 256) sW[i] = W1[i];
    if (t < H1 * C1) { sAs[t] = as_w[t]; sAd[t] = ad_w[t]; }
    __syncthreads();

    int warp = t >> 5, lane = t & 31;
    int h = warp & 3;
    int n = blk * 64 + (warp >> 2) * 32 + lane;
    if (n >= NN) return;

    float xv[16];
    const float4* xp = (const float4*)(x + (size_t)n * IN_CH);
    #pragma unroll
    for (int i = 0; i < 4; i++) {
        float4 r = xp[i];
        xv[4*i]=r.x; xv[4*i+1]=r.y; xv[4*i+2]=r.z; xv[4*i+3]=r.w;
    }
    float acc[C1];
    #pragma unroll
    for (int c = 0; c < C1; c++) acc[c] = 0.f;
    #pragma unroll
    for (int k = 0; k < IN_CH; k++) {
        float xk = xv[k];
        const float* wrow = sW + k * D1 + h * C1;
        #pragma unroll
        for (int c = 0; c < C1; c++) acc[c] += xk * wrow[c];
    }
    float asum = 0.f, dsum = 0.f;
    #pragma unroll
    for (int c = 0; c < C1; c++) { asum += acc[c] * sAs[h*C1+c]; dsum += acc[c] * sAd[h*C1+c]; }
    g_as1[n * H1 + h] = asum;
    g_ad1[n * H1 + h] = dsum;
    uint4 pk[4];
    unsigned* pu = (unsigned*)pk;
    #pragma unroll
    for (int i = 0; i < 16; i++) {
        __half2 hh = __floats2half2_rn(acc[2*i], acc[2*i+1]);
        pu[i] = *(unsigned*)&hh;
    }
    uint4* hp = (uint4*)(g_h1h + (size_t)n * D1 + h * C1);
    #pragma unroll
    for (int i = 0; i < 4; i++) hp[i] = pk[i];
}

// ---------------- scatter + gemm1 fat kernel ----------------
__global__ void __launch_bounds__(256) k_scatter_gemm1(
        const int* __restrict__ ei,
        const float* __restrict__ x,
        const float* __restrict__ W1,
        const float* __restrict__ as_w,
        const float* __restrict__ ad_w) {
    __shared__ float sW[IN_CH * D1 + 2 * H1 * C1];
    int b = blockIdx.x;
    if (b < SCAT_BLOCKS) {
        int idx = b * 256 + threadIdx.x;
        if (idx >= ET) return;
        int src, dst;
        if (idx < EE) { src = ei[idx]; dst = ei[EE + idx]; }
        else          { src = idx - EE; dst = src; }
        int slot = atomicAdd(&g_cursor[dst], 1);
        g_csrsrc[slot] = src;
    } else {
        gemm1_body(b - SCAT_BLOCKS, x, W1, as_w, ad_w,
                   sW, sW + IN_CH * D1, sW + IN_CH * D1 + H1 * C1);
    }
}

__device__ __forceinline__ float lrelu(float e) { return e > 0.f ? e : NEG * e; }
__device__ __forceinline__ float elu(float v)   { return v > 0.f ? v : (__expf(v) - 1.f); }

__device__ __forceinline__ float sel4(float4 a, int q) {
    float w = a.x;
    w = (q == 1) ? a.y : w;
    w = (q == 2) ? a.z : w;
    w = (q == 3) ? a.w : w;
    return w;
}

// ---------------- GAT layer 1: 2 edges/warp-iter, block=128 ----------------
__global__ void __launch_bounds__(128) k_edge1(const float* __restrict__ b1) {
    __shared__ int2 s_pk[4][32][4];
    int w = threadIdx.x >> 5;
    int lane = threadIdx.x & 31;
    int n = blockIdx.x * 4 + w;
    if (n >= NN) return;
    int beg = g_rowptr[n], end = g_rowptr[n + 1];
    float4 ad = *(const float4*)(g_ad1 + n * 4);
    const __half* hbase = g_h1h;

    int grp = lane >> 4;
    int sub = lane & 15;
    int q2  = sub >> 2;
    int choff = sub * 8;

    float s0 = 0.f, s1 = 0.f, s2 = 0.f, s3 = 0.f;
    float a[8];
    #pragma unroll
    for (int k = 0; k < 8; k++) a[k] = 0.f;

    for (int base = beg; base < end; base += 32) {
        int i = base + lane;
        int cnt = min(32, end - base);
        if (i < end) {
            int s = g_csrsrc[i];
            float4 as = *(const float4*)(g_as1 + s * 4);
            float e0 = __expf(lrelu(as.x + ad.x));
            float e1 = __expf(lrelu(as.y + ad.y));
            float e2 = __expf(lrelu(as.z + ad.z));
            float e3 = __expf(lrelu(as.w + ad.w));
            s0 += e0; s1 += e1; s2 += e2; s3 += e3;
            s_pk[w][lane][0] = make_int2(s, __float_as_int(e0));
            s_pk[w][lane][1] = make_int2(s, __float_as_int(e1));
            s_pk[w][lane][2] = make_int2(s, __float_as_int(e2));
            s_pk[w][lane][3] = make_int2(s, __float_as_int(e3));
        }
        __syncwarp();
        int j = 0;
        for (; j + 4 <= cnt; j += 4) {
            int2 pkA = s_pk[w][j + grp][q2];
            int2 pkB = s_pk[w][j + 2 + grp][q2];
            uint4 pA = *(const uint4*)(hbase + (size_t)pkA.x * D1 + choff);
            uint4 pB = *(const uint4*)(hbase + (size_t)pkB.x * D1 + choff);
            float wA = __int_as_float(pkA.y);
            float wB = __int_as_float(pkB.y);
            float2 f;
            f = __half22float2(*(__half2*)&pA.x); a[0] += wA * f.x; a[1] += wA * f.y;
            f = __half22float2(*(__half2*)&pA.y); a[2] += wA * f.x; a[3] += wA * f.y;
            f = __half22float2(*(__half2*)&pA.z); a[4] += wA * f.x; a[5] += wA * f.y;
            f = __half22float2(*(__half2*)&pA.w); a[6] += wA * f.x; a[7] += wA * f.y;
            f = __half22float2(*(__half2*)&pB.x); a[0] += wB * f.x; a[1] += wB * f.y;
            f = __half22float2(*(__half2*)&pB.y); a[2] += wB * f.x; a[3] += wB * f.y;
            f = __half22float2(*(__half2*)&pB.z); a[4] += wB * f.x; a[5] += wB * f.y;
            f = __half22float2(*(__half2*)&pB.w); a[6] += wB * f.x; a[7] += wB * f.y;
        }
        for (; j + 2 <= cnt; j += 2) {
            int2 pk = s_pk[w][j + grp][q2];
            uint4 p = *(const uint4*)(hbase + (size_t)pk.x * D1 + choff);
            float wj = __int_as_float(pk.y);
            float2 f;
            f = __half22float2(*(__half2*)&p.x); a[0] += wj * f.x; a[1] += wj * f.y;
            f = __half22float2(*(__half2*)&p.y); a[2] += wj * f.x; a[3] += wj * f.y;
            f = __half22float2(*(__half2*)&p.z); a[4] += wj * f.x; a[5] += wj * f.y;
            f = __half22float2(*(__half2*)&p.w); a[6] += wj * f.x; a[7] += wj * f.y;
        }
        if (j < cnt && grp == 0) {
            int2 pk = s_pk[w][j][q2];
            uint4 p = *(const uint4*)(hbase + (size_t)pk.x * D1 + choff);
            float wj = __int_as_float(pk.y);
            float2 f;
            f = __half22float2(*(__half2*)&p.x); a[0] += wj * f.x; a[1] += wj * f.y;
            f = __half22float2(*(__half2*)&p.y); a[2] += wj * f.x; a[3] += wj * f.y;
            f = __half22float2(*(__half2*)&p.z); a[4] += wj * f.x; a[5] += wj * f.y;
            f = __half22float2(*(__half2*)&p.w); a[6] += wj * f.x; a[7] += wj * f.y;
        }
        __syncwarp();
    }
    #pragma unroll
    for (int k = 0; k < 8; k++) a[k] += __shfl_xor_sync(0xffffffffu, a[k], 16);
    #pragma unroll
    for (int off = 16; off; off >>= 1) {
        s0 += __shfl_xor_sync(0xffffffffu, s0, off);
        s1 += __shfl_xor_sync(0xffffffffu, s1, off);
        s2 += __shfl_xor_sync(0xffffffffu, s2, off);
        s3 += __shfl_xor_sync(0xffffffffu, s3, off);
    }
    if (grp == 0) {
        float inv = sel4(make_float4(1.f/(s0+1e-16f), 1.f/(s1+1e-16f),
                                     1.f/(s2+1e-16f), 1.f/(s3+1e-16f)), q2);
        const float* bp = b1 + choff;
        uint4 pko;
        unsigned* pu = (unsigned*)&pko;
        #pragma unroll
        for (int k = 0; k < 4; k++) {
            float v0 = elu(a[2*k]   * inv + bp[2*k]);
            float v1 = elu(a[2*k+1] * inv + bp[2*k+1]);
            __half2 hh = __floats2half2_rn(v0, v1);
            pu[k] = *(unsigned*)&hh;
        }
        *(uint4*)(g_out1h + (size_t)n * D1 + choff) = pko;
    }
}

// ---------------- GEMM2 + attention logits (fp16 in, fp16 out) ----------------
__global__ void k_gemm2(const float* __restrict__ W2,
                        const float* __restrict__ as_w,
                        const float* __restrict__ ad_w) {
    __shared__ float sW[D1 * C2];
    __shared__ float sAs[C2], sAd[C2];
    int t = threadIdx.x;
    for (int i = t; i < D1 * C2; i += 256) sW[i] = W2[i];
    if (t < C2) { sAs[t] = as_w[t]; sAd[t] = ad_w[t]; }
    __syncthreads();
    int n = blockIdx.x * blockDim.x + t;
    if (n >= NN) return;

    float acc[C2];
    #pragma unroll
    for (int c = 0; c < C2; c++) acc[c] = 0.f;
    const uint4* xp = (const uint4*)(g_out1h + (size_t)n * D1);
    #pragma unroll 2
    for (int k8 = 0; k8 < 16; k8++) {        // 16 x 8 halves = 128
        uint4 u = xp[k8];
        float2 f0 = __half22float2(*(__half2*)&u.x);
        float2 f1 = __half22float2(*(__half2*)&u.y);
        float2 f2 = __half22float2(*(__half2*)&u.z);
        float2 f3 = __half22float2(*(__half2*)&u.w);
        const float* w0 = sW + (k8 * 8) * C2;
        #pragma unroll
        for (int c = 0; c < C2; c++) {
            acc[c] += f0.x * w0[c]        + f0.y * w0[C2 + c]
                    + f1.x * w0[2*C2 + c] + f1.y * w0[3*C2 + c]
                    + f2.x * w0[4*C2 + c] + f2.y * w0[5*C2 + c]
                    + f3.x * w0[6*C2 + c] + f3.y * w0[7*C2 + c];
        }
    }
    float asum = 0.f, dsum = 0.f;
    #pragma unroll
    for (int c = 0; c < C2; c++) { asum += acc[c] * sAs[c]; dsum += acc[c] * sAd[c]; }
    g_as2[n] = asum;
    g_ad2[n] = dsum;
    uint4 pk[2];
    unsigned* pu = (unsigned*)pk;
    #pragma unroll
    for (int i = 0; i < 8; i++) {
        __half2 hh = __floats2half2_rn(acc[4*(i/2) + 2*(i&1)], acc[4*(i/2) + 2*(i&1) + 1]);
        pu[i] = *(unsigned*)&hh;
    }
    // simpler packing: 16 half2 sequentially
    #pragma unroll
    for (int i = 0; i < 8; i++) {
        __half2 hh = __floats2half2_rn(acc[2*i], acc[2*i+1]);
        pu[i] = *(unsigned*)&hh;
    }
    uint4* hp = (uint4*)(g_h2h + (size_t)n * C2);
    hp[0] = pk[0]; hp[1] = pk[1];
    uint4 pk2[2];
    unsigned* pu2 = (unsigned*)pk2;
    #pragma unroll
    for (int i = 0; i < 8; i++) {
        __half2 hh = __floats2half2_rn(acc[16 + 2*i], acc[16 + 2*i + 1]);
        pu2[i] = *(unsigned*)&hh;
    }
    hp[2] = pk2[0]; hp[3] = pk2[1];
}

// ---------------- GAT layer 2 + pooling: 2 edges/warp-iter, fp16, block=128 ----------------
__global__ void __launch_bounds__(128) k_edge2(const float* __restrict__ b2,
                        const int* __restrict__ batch) {
    __shared__ int2 s_pk[4][32];
    int w = threadIdx.x >> 5;
    int lane = threadIdx.x & 31;
    int n = blockIdx.x * 4 + w;
    if (n >= NN) return;
    int beg = g_rowptr[n], end = g_rowptr[n + 1];
    float ad = g_ad2[n];
    const __half* hbase = g_h2h;

    int grp = lane >> 4;
    int sub = lane & 15;
    int choff = sub * 2;            // 2 channels per lane

    float ssum = 0.f;
    float a0 = 0.f, a1 = 0.f;
    for (int base = beg; base < end; base += 32) {
        int i = base + lane;
        int cnt = min(32, end - base);
        if (i < end) {
            int s = g_csrsrc[i];
            float e = __expf(lrelu(g_as2[s] + ad));
            ssum += e;
            s_pk[w][lane] = make_int2(s, __float_as_int(e));
        }
        __syncwarp();
        int j = 0;
        for (; j + 4 <= cnt; j += 4) {
            int2 pkA = s_pk[w][j + grp];
            int2 pkB = s_pk[w][j + 2 + grp];
            unsigned uA = *(const unsigned*)(hbase + (size_t)pkA.x * C2 + choff);
            unsigned uB = *(const unsigned*)(hbase + (size_t)pkB.x * C2 + choff);
            float wA = __int_as_float(pkA.y);
            float wB = __int_as_float(pkB.y);
            float2 fA = __half22float2(*(__half2*)&uA);
            float2 fB = __half22float2(*(__half2*)&uB);
            a0 += wA * fA.x + wB * fB.x;
            a1 += wA * fA.y + wB * fB.y;
        }
        for (; j + 2 <= cnt; j += 2) {
            int2 pk = s_pk[w][j + grp];
            unsigned u = *(const unsigned*)(hbase + (size_t)pk.x * C2 + choff);
            float wj = __int_as_float(pk.y);
            float2 f = __half22float2(*(__half2*)&u);
            a0 += wj * f.x; a1 += wj * f.y;
        }
        if (j < cnt && grp == 0) {
            int2 pk = s_pk[w][j];
            unsigned u = *(const unsigned*)(hbase + (size_t)pk.x * C2 + choff);
            float wj = __int_as_float(pk.y);
            float2 f = __half22float2(*(__half2*)&u);
            a0 += wj * f.x; a1 += wj * f.y;
        }
        __syncwarp();
    }
    a0 += __shfl_xor_sync(0xffffffffu, a0, 16);
    a1 += __shfl_xor_sync(0xffffffffu, a1, 16);
    #pragma unroll
    for (int off = 16; off; off >>= 1) ssum += __shfl_xor_sync(0xffffffffu, ssum, off);
    float inv = 1.f / (ssum + 1e-16f);
    int gid = batch[n];
    if (grp == 0) {
        float v0 = elu(a0 * inv + b2[choff]);
        float v1 = elu(a1 * inv + b2[choff + 1]);
        float* pp = g_pool + gid * C2 + choff;
        atomicAdd(pp,     v0);
        atomicAdd(pp + 1, v1);
        if (sub == 0) atomicAdd(&g_cnt[gid], 1.0f);
    }
}

// ---------------- MLP head ----------------
__global__ void k_head(const float* __restrict__ Wh1, const float* __restrict__ bh1,
                       const float* __restrict__ Wh2, const float* __restrict__ bh2,
                       float* __restrict__ out) {
    int g = blockIdx.x * blockDim.x + threadIdx.x;
    if (g >= GG) return;
    float cnt = fmaxf(g_cnt[g], 1.0f);
    float invc = 1.f / cnt;
    float p[C2];
    #pragma unroll
    for (int c = 0; c < C2; c++) p[c] = g_pool[g * C2 + c] * invc;
    float o = bh2[0];
    for (int j = 0; j < 64; j++) {
        float a = bh1[j];
        #pragma unroll
        for (int c = 0; c < C2; c++) a += p[c] * Wh1[c * 64 + j];
        a = fmaxf(a, 0.f);
        o += a * Wh2[j];
    }
    out[g] = o;
}

// ---------------- launch ----------------
extern "C" void kernel_launch(void* const* d_in, const int* in_sizes, int n_in,
                              void* d_out, int out_size) {
    const float* x     = (const float*)d_in[0];
    const int*   ei    = (const int*)d_in[1];
    const int*   batch = (const int*)d_in[2];
    const float* W1   = (const float*)d_in[3];
    const float* as1  = (const float*)d_in[4];
    const float* ad1  = (const float*)d_in[5];
    const float* b1   = (const float*)d_in[6];
    const float* W2   = (const float*)d_in[7];
    const float* as2  = (const float*)d_in[8];
    const float* ad2  = (const float*)d_in[9];
    const float* b2   = (const float*)d_in[10];
    const float* Wh1  = (const float*)d_in[11];
    const float* bh1  = (const float*)d_in[12];
    const float* Wh2  = (const float*)d_in[13];
    const float* bh2  = (const float*)d_in[14];
    float* out = (float*)d_out;

    k_degree<<<DEG_BLOCKS + 1, 256>>>(ei);
    k_scan<<<1, 1024>>>();
    k_scatter_gemm1<<<SCAT_BLOCKS + GEMM1_BLOCKS, 256>>>(ei, x, W1, as1, ad1);
    k_edge1<<<(NN + 3) / 4, 128>>>(b1);
    k_gemm2<<<(NN + 255) / 256, 256>>>(W2, as2, ad2);
    k_edge2<<<(NN + 3) / 4, 128>>>(b2, batch);
    k_head<<<1, 128>>>(Wh1, bh1, Wh2, bh2, out);
}